// round 2
// baseline (speedup 1.0000x reference)
#include <cuda_runtime.h>

#define BH 16
#define T 384
#define S 384
#define D 64
#define OUT_ELEMS (BH*T*D)   // 393216

// Scratch projections, row-major: [bh][t][e] and [bh][s][e]
__device__ float4 g_qp4[BH*T*D/4];
__device__ float4 g_kp4[BH*S*D/4];

// ---------------------------------------------------------------------------
// Phase 1: qp[bh][t][e] = sum_d X[bh][t][d] * W[e][d]   (both q and k)
// grid (16 bh, 6 t-chunks of 64, 2 which), 256 threads
// ---------------------------------------------------------------------------
__global__ __launch_bounds__(256) void proj_kernel(
    const float* __restrict__ query, const float* __restrict__ key,
    const float* __restrict__ Wq, const float* __restrict__ Wk)
{
    __shared__ float Xs[64][65];
    __shared__ float Ws[64][65];
    int bh = blockIdx.x, chunk = blockIdx.y, which = blockIdx.z;
    const float* X = which ? key : query;
    const float* W = which ? Wk : Wq;
    float* outp = which ? (float*)g_kp4 : (float*)g_qp4;
    int tid = threadIdx.x;

    for (int i = tid; i < 64*64; i += 256) {
        int r = i >> 6, c = i & 63;
        Xs[r][c] = X[((size_t)bh*T + (size_t)chunk*64 + r)*D + c];
        Ws[r][c] = W[i];
    }
    __syncthreads();

    int t  = tid & 63;        // warp-consecutive t -> conflict-free Xs reads
    int e0 = (tid >> 6) * 16; // same across warp -> Ws broadcast
    float acc[16];
    #pragma unroll
    for (int k = 0; k < 16; k++) acc[k] = 0.f;

    #pragma unroll 4
    for (int d = 0; d < 64; d++) {
        float xv = Xs[t][d];
        #pragma unroll
        for (int k = 0; k < 16; k++)
            acc[k] = fmaf(xv, Ws[e0+k][d], acc[k]);
    }
    float* orow = outp + ((size_t)bh*T + (size_t)chunk*64 + t)*D + e0;
    #pragma unroll
    for (int k = 0; k < 4; k++)
        *(float4*)(orow + 4*k) = make_float4(acc[4*k], acc[4*k+1], acc[4*k+2], acc[4*k+3]);
}

// ---------------------------------------------------------------------------
// Phase 2: fused score(tanh) + softmax + attn@value
// grid (24 t-chunks, 16 bh), 256 threads. One CTA: 16 t-rows x full s=384.
// Per-thread tile 4t x 6s; e processed in 4 chunks of 16, inner groups of 4
// so all smem reads are LDS.128 (10 per 96 tanh).
// ---------------------------------------------------------------------------
#define KP_STRIDE 20   // 16 e-floats + 4 pad -> conflict-free float4 LDS

__global__ __launch_bounds__(256, 4) void attn_kernel(
    const float* __restrict__ value, const float* __restrict__ v_w,
    float* __restrict__ out, float* __restrict__ attn)
{
    __shared__ __align__(16) float sh_kp[S*KP_STRIDE]; // 30720B; aliased as scores[16][384] later
    __shared__ __align__(16) float sh_qp[16][D];       // [t][e]
    __shared__ __align__(16) float4 sh_vw4[16];

    int bh  = blockIdx.y;
    int t0  = blockIdx.x * 16;
    int tid = threadIdx.x;

    // qp tile (16 t x 64 e), coalesced float4
    {
        const float4* qsrc = g_qp4 + ((size_t)bh*T + t0)*(D/4);
        float4* qdst = (float4*)sh_qp;
        for (int i = tid; i < 16*D/4; i += 256) qdst[i] = qsrc[i];
        if (tid < 16) sh_vw4[tid] = ((const float4*)v_w)[tid];
    }

    int sx = tid & 63;   // s lane
    int ty = tid >> 6;   // t group (constant per warp -> qp broadcast)

    float acc[4][6];
    #pragma unroll
    for (int k = 0; k < 4; k++)
        #pragma unroll
        for (int j = 0; j < 6; j++) acc[k][j] = 0.f;

    const float4* kbase4 = g_kp4 + (size_t)bh*S*(D/4);

    for (int c = 0; c < 4; c++) {
        __syncthreads();
        // load kp e-chunk [s:384][e:16] into padded rows, 4x float4 per row
        #pragma unroll
        for (int i = tid; i < S*4; i += 256) {
            int s = i >> 2, q = i & 3;
            float4 v = kbase4[(size_t)s*(D/4) + c*4 + q];
            *(float4*)&sh_kp[s*KP_STRIDE + q*4] = v;
        }
        __syncthreads();

        #pragma unroll
        for (int ecg = 0; ecg < 4; ecg++) {
            float4 vw4 = sh_vw4[c*4 + ecg];
            float4 qv[4];
            #pragma unroll
            for (int k = 0; k < 4; k++)
                qv[k] = *(const float4*)&sh_qp[ty*4 + k][c*16 + ecg*4];
            #pragma unroll
            for (int j = 0; j < 6; j++) {
                float4 kv = *(const float4*)&sh_kp[(sx + 64*j)*KP_STRIDE + ecg*4];
                #pragma unroll
                for (int k = 0; k < 4; k++) {
                    float th;
                    asm("tanh.approx.f32 %0, %1;" : "=f"(th) : "f"(qv[k].x + kv.x));
                    acc[k][j] = fmaf(vw4.x, th, acc[k][j]);
                    asm("tanh.approx.f32 %0, %1;" : "=f"(th) : "f"(qv[k].y + kv.y));
                    acc[k][j] = fmaf(vw4.y, th, acc[k][j]);
                    asm("tanh.approx.f32 %0, %1;" : "=f"(th) : "f"(qv[k].z + kv.z));
                    acc[k][j] = fmaf(vw4.z, th, acc[k][j]);
                    asm("tanh.approx.f32 %0, %1;" : "=f"(th) : "f"(qv[k].w + kv.w));
                    acc[k][j] = fmaf(vw4.w, th, acc[k][j]);
                }
            }
        }
    }
    __syncthreads();

    // dump scores into the (now free) kp buffer
    float (*scores)[384] = (float(*)[384])sh_kp;
    #pragma unroll
    for (int k = 0; k < 4; k++)
        #pragma unroll
        for (int j = 0; j < 6; j++)
            scores[ty*4+k][sx + 64*j] = acc[k][j];
    __syncthreads();

    // softmax: 8 warps, 2 rows each; write attn to global, keep normalized in smem
    int w = tid >> 5, lane = tid & 31;
    for (int r = w; r < 16; r += 8) {
        float vals[12];
        float m = -1e30f;
        #pragma unroll
        for (int i = 0; i < 12; i++) {
            vals[i] = scores[r][lane + 32*i];
            m = fmaxf(m, vals[i]);
        }
        #pragma unroll
        for (int off = 16; off; off >>= 1)
            m = fmaxf(m, __shfl_xor_sync(0xffffffffu, m, off));
        float sum = 0.f;
        #pragma unroll
        for (int i = 0; i < 12; i++) {
            float p;
            float xe = (vals[i] - m) * 1.4426950408889634f;
            asm("ex2.approx.f32 %0, %1;" : "=f"(p) : "f"(xe));
            vals[i] = p;
            sum += p;
        }
        #pragma unroll
        for (int off = 16; off; off >>= 1)
            sum += __shfl_xor_sync(0xffffffffu, sum, off);
        float inv = 1.0f / sum;
        size_t arow = ((size_t)bh*T + t0 + r) * S;
        #pragma unroll
        for (int i = 0; i < 12; i++) {
            float p = vals[i] * inv;
            scores[r][lane + 32*i] = p;
            attn[arow + lane + 32*i] = p;
        }
    }
    __syncthreads();

    // epilogue: out[t0+tl][d] = sum_s attn[tl][s] * value[s][d]
    int dx = sx; // 0..63, warp-coalesced value loads
    float acc2[4] = {0.f, 0.f, 0.f, 0.f};
    const float* vp = value + (size_t)bh*S*D + dx;
    #pragma unroll 2
    for (int s = 0; s < 384; s += 4) {
        float v0 = __ldg(vp + (size_t)(s+0)*D);
        float v1 = __ldg(vp + (size_t)(s+1)*D);
        float v2 = __ldg(vp + (size_t)(s+2)*D);
        float v3 = __ldg(vp + (size_t)(s+3)*D);
        #pragma unroll
        for (int k = 0; k < 4; k++) {
            float4 a = *(const float4*)&scores[ty*4+k][s];
            acc2[k] = fmaf(a.x, v0, fmaf(a.y, v1, fmaf(a.z, v2, fmaf(a.w, v3, acc2[k]))));
        }
    }
    #pragma unroll
    for (int k = 0; k < 4; k++)
        out[((size_t)bh*T + t0 + ty*4 + k)*D + dx] = acc2[k];
}

// ---------------------------------------------------------------------------
extern "C" void kernel_launch(void* const* d_in, const int* in_sizes, int n_in,
                              void* d_out, int out_size)
{
    (void)in_sizes; (void)n_in; (void)out_size;
    const float* query = (const float*)d_in[0];
    const float* key   = (const float*)d_in[1];
    const float* value = (const float*)d_in[2];
    const float* Wq    = (const float*)d_in[3];
    const float* Wk    = (const float*)d_in[4];
    const float* vw    = (const float*)d_in[5];
    float* out  = (float*)d_out;
    float* attn = out + OUT_ELEMS;

    proj_kernel<<<dim3(16, 6, 2), 256>>>(query, key, Wq, Wk);
    attn_kernel<<<dim3(24, 16), 256>>>(value, vw, out, attn);
}

// round 3
// speedup vs baseline: 1.0131x; 1.0131x over previous
#include <cuda_runtime.h>

#define BH 16
#define T 384
#define S 384
#define D 64
#define OUT_ELEMS (BH*T*D)   // 393216

// Scratch projections, row-major: [bh][t][e] and [bh][s][e]
__device__ float4 g_qp4[BH*T*D/4];
__device__ float4 g_kp4[BH*S*D/4];

// ---------------------------------------------------------------------------
// Phase 1: qp[bh][t][e] = sum_d X[bh][t][d] * W[e][d]   (both q and k)
// ---------------------------------------------------------------------------
__global__ __launch_bounds__(256) void proj_kernel(
    const float* __restrict__ query, const float* __restrict__ key,
    const float* __restrict__ Wq, const float* __restrict__ Wk)
{
    __shared__ float Xs[64][65];
    __shared__ float Ws[64][65];
    int bh = blockIdx.x, chunk = blockIdx.y, which = blockIdx.z;
    const float* X = which ? key : query;
    const float* W = which ? Wk : Wq;
    float* outp = which ? (float*)g_kp4 : (float*)g_qp4;
    int tid = threadIdx.x;

    for (int i = tid; i < 64*64; i += 256) {
        int r = i >> 6, c = i & 63;
        Xs[r][c] = X[((size_t)bh*T + (size_t)chunk*64 + r)*D + c];
        Ws[r][c] = W[i];
    }
    __syncthreads();

    int t  = tid & 63;
    int e0 = (tid >> 6) * 16;
    float acc[16];
    #pragma unroll
    for (int k = 0; k < 16; k++) acc[k] = 0.f;

    #pragma unroll 4
    for (int d = 0; d < 64; d++) {
        float xv = Xs[t][d];
        #pragma unroll
        for (int k = 0; k < 16; k++)
            acc[k] = fmaf(xv, Ws[e0+k][d], acc[k]);
    }
    float* orow = outp + ((size_t)bh*T + (size_t)chunk*64 + t)*D + e0;
    #pragma unroll
    for (int k = 0; k < 4; k++)
        *(float4*)(orow + 4*k) = make_float4(acc[4*k], acc[4*k+1], acc[4*k+2], acc[4*k+3]);
}

// ---------------------------------------------------------------------------
// Phase 2: fused score(tanh) + softmax + attn@value
// grid (24, 16), 256 thr. CTA: 16 t x 384 s. kp streamed as 8 chunks of 8 e
// through a cp.async double buffer so the copy of chunk c+1 overlaps compute
// of chunk c. Row stride 12 floats -> conflict-free LDS.128.
// ---------------------------------------------------------------------------
#define KP_STRIDE 12
#define CHUNK_FLOATS (S*KP_STRIDE)   // 4608 floats = 18432 B

__device__ __forceinline__ unsigned smem_u32(const void* p) {
    return (unsigned)__cvta_generic_to_shared(p);
}

__global__ __launch_bounds__(256) void attn_kernel(
    const float* __restrict__ value, const float* __restrict__ v_w,
    float* __restrict__ out, float* __restrict__ attn)
{
    __shared__ __align__(16) float sh_kp[2*CHUNK_FLOATS]; // 36864 B; aliased as scores[16][384] later
    __shared__ __align__(16) float sh_qp[16][D];
    __shared__ __align__(16) float4 sh_vw4[16];

    int bh  = blockIdx.y;
    int t0  = blockIdx.x * 16;
    int tid = threadIdx.x;

    {   // qp tile (16 t x 64 e), coalesced float4
        const float4* qsrc = g_qp4 + ((size_t)bh*T + t0)*(D/4);
        float4* qdst = (float4*)sh_qp;
        for (int i = tid; i < 16*D/4; i += 256) qdst[i] = qsrc[i];
        if (tid < 16) sh_vw4[tid] = ((const float4*)v_w)[tid];
    }

    const float4* kbase4 = g_kp4 + (size_t)bh*S*(D/4);

    // async load of chunk c (8 e-cols) into buffer b: 768 float4, 3/thread
    auto issue_chunk = [&](int c, int b) {
        #pragma unroll
        for (int r = 0; r < 3; r++) {
            int i = tid + r*256;           // 0..767
            int s = i >> 1, q = i & 1;
            unsigned dst = smem_u32(&sh_kp[b*CHUNK_FLOATS + s*KP_STRIDE + q*4]);
            const float4* src = kbase4 + (size_t)s*(D/4) + c*2 + q;
            asm volatile("cp.async.ca.shared.global [%0], [%1], 16;\n"
                         :: "r"(dst), "l"(src));
        }
    };

    int sx = tid & 63;   // s lane
    int ty = tid >> 6;   // t group (constant per warp -> qp broadcast)

    float acc[4][6];
    #pragma unroll
    for (int k = 0; k < 4; k++)
        #pragma unroll
        for (int j = 0; j < 6; j++) acc[k][j] = 0.f;

    issue_chunk(0, 0);
    asm volatile("cp.async.commit_group;\n");
    issue_chunk(1, 1);
    asm volatile("cp.async.commit_group;\n");

    for (int c = 0; c < 8; c++) {
        asm volatile("cp.async.wait_group 1;\n");   // chunk c complete, c+1 may fly
        __syncthreads();

        const float* buf = &sh_kp[(c & 1)*CHUNK_FLOATS];
        #pragma unroll
        for (int ecg = 0; ecg < 2; ecg++) {
            float4 vw4 = sh_vw4[c*2 + ecg];
            float4 qv[4];
            #pragma unroll
            for (int k = 0; k < 4; k++)
                qv[k] = *(const float4*)&sh_qp[ty*4 + k][c*8 + ecg*4];
            #pragma unroll
            for (int j = 0; j < 6; j++) {
                float4 kv = *(const float4*)&buf[(sx + 64*j)*KP_STRIDE + ecg*4];
                #pragma unroll
                for (int k = 0; k < 4; k++) {
                    float th;
                    asm("tanh.approx.f32 %0, %1;" : "=f"(th) : "f"(qv[k].x + kv.x));
                    acc[k][j] = fmaf(vw4.x, th, acc[k][j]);
                    asm("tanh.approx.f32 %0, %1;" : "=f"(th) : "f"(qv[k].y + kv.y));
                    acc[k][j] = fmaf(vw4.y, th, acc[k][j]);
                    asm("tanh.approx.f32 %0, %1;" : "=f"(th) : "f"(qv[k].z + kv.z));
                    acc[k][j] = fmaf(vw4.z, th, acc[k][j]);
                    asm("tanh.approx.f32 %0, %1;" : "=f"(th) : "f"(qv[k].w + kv.w));
                    acc[k][j] = fmaf(vw4.w, th, acc[k][j]);
                }
            }
        }
        __syncthreads();   // everyone done reading buf[c&1] before overwrite
        if (c + 2 < 8) issue_chunk(c + 2, c & 1);
        asm volatile("cp.async.commit_group;\n");   // one group per iter (may be empty)
    }

    __syncthreads();

    // dump scores into the (now free) kp buffers
    float (*scores)[384] = (float(*)[384])sh_kp;
    #pragma unroll
    for (int k = 0; k < 4; k++)
        #pragma unroll
        for (int j = 0; j < 6; j++)
            scores[ty*4+k][sx + 64*j] = acc[k][j];
    __syncthreads();

    // softmax: 8 warps, 2 rows each
    int w = tid >> 5, lane = tid & 31;
    for (int r = w; r < 16; r += 8) {
        float vals[12];
        float m = -1e30f;
        #pragma unroll
        for (int i = 0; i < 12; i++) {
            vals[i] = scores[r][lane + 32*i];
            m = fmaxf(m, vals[i]);
        }
        #pragma unroll
        for (int off = 16; off; off >>= 1)
            m = fmaxf(m, __shfl_xor_sync(0xffffffffu, m, off));
        float sum = 0.f;
        #pragma unroll
        for (int i = 0; i < 12; i++) {
            float p;
            float xe = (vals[i] - m) * 1.4426950408889634f;
            asm("ex2.approx.f32 %0, %1;" : "=f"(p) : "f"(xe));
            vals[i] = p;
            sum += p;
        }
        #pragma unroll
        for (int off = 16; off; off >>= 1)
            sum += __shfl_xor_sync(0xffffffffu, sum, off);
        float inv = 1.0f / sum;
        size_t arow = ((size_t)bh*T + t0 + r) * S;
        #pragma unroll
        for (int i = 0; i < 12; i++) {
            float p = vals[i] * inv;
            scores[r][lane + 32*i] = p;
            attn[arow + lane + 32*i] = p;
        }
    }
    __syncthreads();

    // epilogue: out[t0+tl][d] = sum_s attn[tl][s] * value[s][d]
    int dx = sx;
    float acc2[4] = {0.f, 0.f, 0.f, 0.f};
    const float* vp = value + (size_t)bh*S*D + dx;
    #pragma unroll 2
    for (int s = 0; s < 384; s += 4) {
        float v0 = __ldg(vp + (size_t)(s+0)*D);
        float v1 = __ldg(vp + (size_t)(s+1)*D);
        float v2 = __ldg(vp + (size_t)(s+2)*D);
        float v3 = __ldg(vp + (size_t)(s+3)*D);
        #pragma unroll
        for (int k = 0; k < 4; k++) {
            float4 a = *(const float4*)&scores[ty*4+k][s];
            acc2[k] = fmaf(a.x, v0, fmaf(a.y, v1, fmaf(a.z, v2, fmaf(a.w, v3, acc2[k]))));
        }
    }
    #pragma unroll
    for (int k = 0; k < 4; k++)
        out[((size_t)bh*T + t0 + ty*4 + k)*D + dx] = acc2[k];
}

// ---------------------------------------------------------------------------
extern "C" void kernel_launch(void* const* d_in, const int* in_sizes, int n_in,
                              void* d_out, int out_size)
{
    (void)in_sizes; (void)n_in; (void)out_size;
    const float* query = (const float*)d_in[0];
    const float* key   = (const float*)d_in[1];
    const float* value = (const float*)d_in[2];
    const float* Wq    = (const float*)d_in[3];
    const float* Wk    = (const float*)d_in[4];
    const float* vw    = (const float*)d_in[5];
    float* out  = (float*)d_out;
    float* attn = out + OUT_ELEMS;

    proj_kernel<<<dim3(16, 6, 2), 256>>>(query, key, Wq, Wk);
    attn_kernel<<<dim3(24, 16), 256>>>(value, vw, out, attn);
}

// round 5
// speedup vs baseline: 1.0532x; 1.0395x over previous
#include <cuda_runtime.h>

#define BH 16
#define T 384
#define S 384
#define D 64
#define OUT_ELEMS (BH*T*D)   // 393216

// Scratch projections, e-major: [bh][e][t] / [bh][e][s]
__device__ float4 g_qpT4[BH*D*T/4];
__device__ float4 g_kpT4[BH*D*S/4];

// ---------------------------------------------------------------------------
// Phase 1: qpT[bh][e][t] = sum_d X[bh][t][d] * W[e][d]   (both q and k)
// grid (16 bh, 6 t-chunks of 64, 2 which), 256 threads
// ---------------------------------------------------------------------------
__global__ __launch_bounds__(256) void proj_kernel(
    const float* __restrict__ query, const float* __restrict__ key,
    const float* __restrict__ Wq, const float* __restrict__ Wk)
{
    __shared__ float Xs[64][65];
    __shared__ float Ws[64][65];
    int bh = blockIdx.x, chunk = blockIdx.y, which = blockIdx.z;
    const float* X = which ? key : query;
    const float* W = which ? Wk : Wq;
    float* outT = which ? (float*)g_kpT4 : (float*)g_qpT4;
    int tid = threadIdx.x;

    for (int i = tid; i < 64*64; i += 256) {
        int r = i >> 6, c = i & 63;
        Xs[r][c] = X[((size_t)bh*T + (size_t)chunk*64 + r)*D + c];
        Ws[r][c] = W[i];
    }
    __syncthreads();

    int t  = tid & 63;        // warp-consecutive -> conflict-free Xs
    int e0 = (tid >> 6) * 16; // warp-uniform -> Ws broadcast
    float acc[16];
    #pragma unroll
    for (int k = 0; k < 16; k++) acc[k] = 0.f;

    #pragma unroll 4
    for (int d = 0; d < 64; d++) {
        float xv = Xs[t][d];
        #pragma unroll
        for (int k = 0; k < 16; k++)
            acc[k] = fmaf(xv, Ws[e0+k][d], acc[k]);
    }
    #pragma unroll
    for (int k = 0; k < 16; k++)
        outT[((size_t)bh*D + e0 + k)*T + (size_t)chunk*64 + t] = acc[k];
}

// ---------------------------------------------------------------------------
// Phase 2: fused score(tanh) + softmax + attn@value
// grid (48 t-chunks, 16 bh), 128 threads. One CTA: 8 t-rows x full s=384.
// Per-thread tile 4t x 6s (ty in {0,1}); kp streamed in 4 sync chunks of 16 e.
// 768 CTAs x 4 warps -> ~28-32 warps/SM resident (vs 20 before).
// ---------------------------------------------------------------------------
__global__ __launch_bounds__(128) void attn_kernel(
    const float* __restrict__ value, const float* __restrict__ v_w,
    float* __restrict__ out, float* __restrict__ attn)
{
    __shared__ __align__(16) float sh_kp[16*384]; // 24KB; aliased as scores[8][384] later
    __shared__ float sh_qp[64][8];
    __shared__ float sh_vw[64];

    int bh  = blockIdx.y;
    int t0  = blockIdx.x * 8;
    int tid = threadIdx.x;

    // qp tile (64 e x 8 t) + v_w
    const float* qbase = (const float*)g_qpT4 + (size_t)bh*D*T;
    for (int i = tid; i < 64*8; i += 128) {
        int e = i >> 3, tl = i & 7;
        sh_qp[e][tl] = qbase[(size_t)e*T + t0 + tl];
    }
    if (tid < 64) sh_vw[tid] = v_w[tid];

    int sx = tid & 63;   // s lane (warp-consecutive -> conflict-free kp LDS)
    int ty = tid >> 6;   // t group (warp-uniform -> qp broadcast)

    float acc[4][6];
    #pragma unroll
    for (int k = 0; k < 4; k++)
        #pragma unroll
        for (int j = 0; j < 6; j++) acc[k][j] = 0.f;

    const float4* kbase4 = g_kpT4 + (size_t)bh*D*S/4;

    for (int c = 0; c < 4; c++) {
        __syncthreads();
        // load kp chunk: 16 e-rows x 384 s (24 KB), coalesced float4, 12/thread
        const float4* src = kbase4 + (size_t)c*16*S/4;
        float4* dst = (float4*)sh_kp;
        #pragma unroll
        for (int i = tid; i < 16*384/4; i += 128) dst[i] = src[i];
        __syncthreads();

        #pragma unroll
        for (int ec = 0; ec < 16; ec++) {
            int e = c*16 + ec;
            float vw = sh_vw[e];
            float qv[4], kv[6];
            #pragma unroll
            for (int k = 0; k < 4; k++) qv[k] = sh_qp[e][ty*4+k];
            #pragma unroll
            for (int j = 0; j < 6; j++) kv[j] = sh_kp[ec*384 + sx + 64*j];
            #pragma unroll
            for (int k = 0; k < 4; k++)
                #pragma unroll
                for (int j = 0; j < 6; j++) {
                    float x = qv[k] + kv[j];
                    float th;
                    asm("tanh.approx.f32 %0, %1;" : "=f"(th) : "f"(x));
                    acc[k][j] = fmaf(vw, th, acc[k][j]);
                }
        }
    }
    __syncthreads();

    // dump scores into the (now free) kp buffer
    float (*scores)[384] = (float(*)[384])sh_kp;
    #pragma unroll
    for (int k = 0; k < 4; k++)
        #pragma unroll
        for (int j = 0; j < 6; j++)
            scores[ty*4+k][sx + 64*j] = acc[k][j];
    __syncthreads();

    // softmax: 4 warps, 2 rows each; write attn to global, keep normalized in smem
    int w = tid >> 5, lane = tid & 31;
    for (int r = w; r < 8; r += 4) {
        float vals[12];
        float m = -1e30f;
        #pragma unroll
        for (int i = 0; i < 12; i++) {
            vals[i] = scores[r][lane + 32*i];
            m = fmaxf(m, vals[i]);
        }
        #pragma unroll
        for (int off = 16; off; off >>= 1)
            m = fmaxf(m, __shfl_xor_sync(0xffffffffu, m, off));
        float sum = 0.f;
        #pragma unroll
        for (int i = 0; i < 12; i++) {
            float p;
            float xe = (vals[i] - m) * 1.4426950408889634f;
            asm("ex2.approx.f32 %0, %1;" : "=f"(p) : "f"(xe));
            vals[i] = p;
            sum += p;
        }
        #pragma unroll
        for (int off = 16; off; off >>= 1)
            sum += __shfl_xor_sync(0xffffffffu, sum, off);
        float inv = 1.0f / sum;
        size_t arow = ((size_t)bh*T + t0 + r) * S;
        #pragma unroll
        for (int i = 0; i < 12; i++) {
            float p = vals[i] * inv;
            scores[r][lane + 32*i] = p;
            attn[arow + lane + 32*i] = p;
        }
    }
    __syncthreads();

    // epilogue: out[t0+tl][d] = sum_s attn[tl][s] * value[s][d]
    int dx = sx; // 0..63, warp-coalesced value loads
    float acc2[4] = {0.f, 0.f, 0.f, 0.f};
    const float* vp = value + (size_t)bh*S*D + dx;
    #pragma unroll 2
    for (int s = 0; s < 384; s += 4) {
        float v0 = __ldg(vp + (size_t)(s+0)*D);
        float v1 = __ldg(vp + (size_t)(s+1)*D);
        float v2 = __ldg(vp + (size_t)(s+2)*D);
        float v3 = __ldg(vp + (size_t)(s+3)*D);
        #pragma unroll
        for (int k = 0; k < 4; k++) {
            float4 a = *(const float4*)&scores[ty*4+k][s];
            acc2[k] = fmaf(a.x, v0, fmaf(a.y, v1, fmaf(a.z, v2, fmaf(a.w, v3, acc2[k]))));
        }
    }
    #pragma unroll
    for (int k = 0; k < 4; k++)
        out[((size_t)bh*T + t0 + ty*4 + k)*D + dx] = acc2[k];
}

// ---------------------------------------------------------------------------
extern "C" void kernel_launch(void* const* d_in, const int* in_sizes, int n_in,
                              void* d_out, int out_size)
{
    (void)in_sizes; (void)n_in; (void)out_size;
    const float* query = (const float*)d_in[0];
    const float* key   = (const float*)d_in[1];
    const float* value = (const float*)d_in[2];
    const float* Wq    = (const float*)d_in[3];
    const float* Wk    = (const float*)d_in[4];
    const float* vw    = (const float*)d_in[5];
    float* out  = (float*)d_out;
    float* attn = out + OUT_ELEMS;

    proj_kernel<<<dim3(16, 6, 2), 256>>>(query, key, Wq, Wk);
    attn_kernel<<<dim3(48, 16), 128>>>(value, vw, out, attn);
}

// round 6
// speedup vs baseline: 1.0842x; 1.0295x over previous
#include <cuda_runtime.h>
#include <cuda_fp16.h>

#define BH 16
#define T 384
#define S 384
#define D 64
#define OUT_ELEMS (BH*T*D)   // 393216

// Scratch projections, e-major: qp fp32 [bh][e][t]; kp fp16 [bh][e][s]
__device__ float4 g_qpT4[BH*D*T/4];
__device__ uint4  g_kpTh4[BH*D*S/8];   // __half storage, uint4 for staging

// ---------------------------------------------------------------------------
// Phase 1: qpT[bh][e][t] = sum_d X[bh][t][d] * W[e][d]   (both q and k)
// grid (16 bh, 6 t-chunks of 64, 2 which), 256 threads
// ---------------------------------------------------------------------------
__global__ __launch_bounds__(256) void proj_kernel(
    const float* __restrict__ query, const float* __restrict__ key,
    const float* __restrict__ Wq, const float* __restrict__ Wk)
{
    __shared__ float Xs[64][65];
    __shared__ float Ws[64][65];
    int bh = blockIdx.x, chunk = blockIdx.y, which = blockIdx.z;
    const float* X = which ? key : query;
    const float* W = which ? Wk : Wq;
    int tid = threadIdx.x;

    for (int i = tid; i < 64*64; i += 256) {
        int r = i >> 6, c = i & 63;
        Xs[r][c] = X[((size_t)bh*T + (size_t)chunk*64 + r)*D + c];
        Ws[r][c] = W[i];
    }
    __syncthreads();

    int t  = tid & 63;        // warp-consecutive -> conflict-free Xs
    int e0 = (tid >> 6) * 16; // warp-uniform -> Ws broadcast
    float acc[16];
    #pragma unroll
    for (int k = 0; k < 16; k++) acc[k] = 0.f;

    #pragma unroll 4
    for (int d = 0; d < 64; d++) {
        float xv = Xs[t][d];
        #pragma unroll
        for (int k = 0; k < 16; k++)
            acc[k] = fmaf(xv, Ws[e0+k][d], acc[k]);
    }

    if (which) {   // key path -> fp16
        __half* outTh = (__half*)g_kpTh4;
        #pragma unroll
        for (int k = 0; k < 16; k++)
            outTh[((size_t)bh*D + e0 + k)*S + (size_t)chunk*64 + t] = __float2half_rn(acc[k]);
    } else {       // query path -> fp32
        float* outT = (float*)g_qpT4;
        #pragma unroll
        for (int k = 0; k < 16; k++)
            outT[((size_t)bh*D + e0 + k)*T + (size_t)chunk*64 + t] = acc[k];
    }
}

// ---------------------------------------------------------------------------
// Phase 2: fused score(tanh.f16x2) + softmax + attn@value
// grid (48 t-chunks, 16 bh), 128 threads. One CTA: 8 t x 384 s.
// Thread tile 4t x 3 s-pairs (6 s). kp streamed in 4 sync chunks of 16 e.
// Each tanh.approx.f16x2 covers 2 elements -> halves MUFU.TANH pressure.
// ---------------------------------------------------------------------------
__global__ __launch_bounds__(128) void attn_kernel(
    const float* __restrict__ value, const float* __restrict__ v_w,
    float* __restrict__ out, float* __restrict__ attn)
{
    // kp chunk (16 e x 192 half2 = 12288 B), later aliased as scores[8][384] f32
    __shared__ __align__(16) unsigned char sh_raw[16*192*4];
    __shared__ __align__(8) __half2 sh_qph[64][8];   // (h,h) broadcast pairs
    __shared__ float sh_vw[64];

    __half2 (*kph)[192] = (__half2(*)[192])sh_raw;
    float  (*scores)[384] = (float(*)[384])sh_raw;

    int bh  = blockIdx.y;
    int t0  = blockIdx.x * 8;
    int tid = threadIdx.x;

    // stage qp tile as f16x2 broadcast pairs + v_w
    const float* qbase = (const float*)g_qpT4 + (size_t)bh*D*T;
    for (int i = tid; i < 64*8; i += 128) {
        int e = i >> 3, tl = i & 7;
        __half h = __float2half_rn(qbase[(size_t)e*T + t0 + tl]);
        sh_qph[e][tl] = __half2half2(h);
    }
    if (tid < 64) sh_vw[tid] = v_w[tid];

    int sx = tid & 63;   // s-pair lane
    int ty = tid >> 6;   // t group (warp-uniform -> qph broadcast)

    float acc[4][6];
    #pragma unroll
    for (int k = 0; k < 4; k++)
        #pragma unroll
        for (int j = 0; j < 6; j++) acc[k][j] = 0.f;

    const uint4* kbase = g_kpTh4 + (size_t)bh*D*S/8;

    for (int c = 0; c < 4; c++) {
        __syncthreads();
        // load kp chunk: 16 e-rows x 384 halfs = 768 uint4, 6/thread
        const uint4* src = kbase + (size_t)c*16*S/8;
        uint4* dst = (uint4*)sh_raw;
        #pragma unroll
        for (int i = tid; i < 768; i += 128) dst[i] = src[i];
        __syncthreads();

        #pragma unroll
        for (int ec = 0; ec < 16; ec++) {
            int e = c*16 + ec;
            float vw = sh_vw[e];
            __half2 q2[4], kk[3];
            #pragma unroll
            for (int k = 0; k < 4; k++) q2[k] = sh_qph[e][ty*4 + k];
            #pragma unroll
            for (int p = 0; p < 3; p++) kk[p] = kph[ec][sx + 64*p];
            #pragma unroll
            for (int k = 0; k < 4; k++)
                #pragma unroll
                for (int p = 0; p < 3; p++) {
                    __half2 x = __hadd2(q2[k], kk[p]);
                    unsigned xo, xi = *(unsigned*)&x;
                    asm("tanh.approx.f16x2 %0, %1;" : "=r"(xo) : "r"(xi));
                    __half2 th = *(__half2*)&xo;
                    acc[k][2*p]   = fmaf(vw, __low2float(th),  acc[k][2*p]);
                    acc[k][2*p+1] = fmaf(vw, __high2float(th), acc[k][2*p+1]);
                }
        }
    }
    __syncthreads();

    // dump scores (thread's s values: 2*sx + 128*p and +1) into aliased buffer
    #pragma unroll
    for (int k = 0; k < 4; k++)
        #pragma unroll
        for (int p = 0; p < 3; p++) {
            scores[ty*4+k][2*sx   + 128*p] = acc[k][2*p];
            scores[ty*4+k][2*sx+1 + 128*p] = acc[k][2*p+1];
        }
    __syncthreads();

    // softmax: 4 warps, 2 rows each; write attn to global, keep normalized in smem
    int w = tid >> 5, lane = tid & 31;
    for (int r = w; r < 8; r += 4) {
        float vals[12];
        float m = -1e30f;
        #pragma unroll
        for (int i = 0; i < 12; i++) {
            vals[i] = scores[r][lane + 32*i];
            m = fmaxf(m, vals[i]);
        }
        #pragma unroll
        for (int off = 16; off; off >>= 1)
            m = fmaxf(m, __shfl_xor_sync(0xffffffffu, m, off));
        float sum = 0.f;
        #pragma unroll
        for (int i = 0; i < 12; i++) {
            float p;
            float xe = (vals[i] - m) * 1.4426950408889634f;
            asm("ex2.approx.f32 %0, %1;" : "=f"(p) : "f"(xe));
            vals[i] = p;
            sum += p;
        }
        #pragma unroll
        for (int off = 16; off; off >>= 1)
            sum += __shfl_xor_sync(0xffffffffu, sum, off);
        float inv = 1.0f / sum;
        size_t arow = ((size_t)bh*T + t0 + r) * S;
        #pragma unroll
        for (int i = 0; i < 12; i++) {
            float p = vals[i] * inv;
            scores[r][lane + 32*i] = p;
            attn[arow + lane + 32*i] = p;
        }
    }
    __syncthreads();

    // epilogue: out[t0+tl][d] = sum_s attn[tl][s] * value[s][d]
    int dx = sx; // 0..63, warp-coalesced value loads
    float acc2[4] = {0.f, 0.f, 0.f, 0.f};
    const float* vp = value + (size_t)bh*S*D + dx;
    #pragma unroll 2
    for (int s = 0; s < 384; s += 4) {
        float v0 = __ldg(vp + (size_t)(s+0)*D);
        float v1 = __ldg(vp + (size_t)(s+1)*D);
        float v2 = __ldg(vp + (size_t)(s+2)*D);
        float v3 = __ldg(vp + (size_t)(s+3)*D);
        #pragma unroll
        for (int k = 0; k < 4; k++) {
            float4 a = *(const float4*)&scores[ty*4+k][s];
            acc2[k] = fmaf(a.x, v0, fmaf(a.y, v1, fmaf(a.z, v2, fmaf(a.w, v3, acc2[k]))));
        }
    }
    #pragma unroll
    for (int k = 0; k < 4; k++)
        out[((size_t)bh*T + t0 + ty*4 + k)*D + dx] = acc2[k];
}

// ---------------------------------------------------------------------------
extern "C" void kernel_launch(void* const* d_in, const int* in_sizes, int n_in,
                              void* d_out, int out_size)
{
    (void)in_sizes; (void)n_in; (void)out_size;
    const float* query = (const float*)d_in[0];
    const float* key   = (const float*)d_in[1];
    const float* value = (const float*)d_in[2];
    const float* Wq    = (const float*)d_in[3];
    const float* Wk    = (const float*)d_in[4];
    const float* vw    = (const float*)d_in[5];
    float* out  = (float*)d_out;
    float* attn = out + OUT_ELEMS;

    proj_kernel<<<dim3(16, 6, 2), 256>>>(query, key, Wq, Wk);
    attn_kernel<<<dim3(48, 16), 128>>>(value, vw, out, attn);
}

// round 7
// speedup vs baseline: 1.0847x; 1.0005x over previous
#include <cuda_runtime.h>
#include <cuda_fp16.h>

#define BH 16
#define T 384
#define S 384
#define D 64
#define OUT_ELEMS (BH*T*D)   // 393216

// Scratch projections, e-major: qp fp32 [bh][e][t]; kp fp16 [bh][e][s]
__device__ float4 g_qpT4[BH*D*T/4];
__device__ uint4  g_kpTh4[BH*D*S/8];   // __half storage, uint4 for staging

// ---------------------------------------------------------------------------
// Phase 1: qpT[bh][e][t] = sum_d X[bh][t][d] * W[e][d]   (both q and k)
// grid (16 bh, 6 t-chunks of 64, 2 which), 256 threads
// ---------------------------------------------------------------------------
__global__ __launch_bounds__(256) void proj_kernel(
    const float* __restrict__ query, const float* __restrict__ key,
    const float* __restrict__ Wq, const float* __restrict__ Wk)
{
    __shared__ float Xs[64][65];
    __shared__ float Ws[64][65];
    int bh = blockIdx.x, chunk = blockIdx.y, which = blockIdx.z;
    const float* X = which ? key : query;
    const float* W = which ? Wk : Wq;
    int tid = threadIdx.x;

    for (int i = tid; i < 64*64; i += 256) {
        int r = i >> 6, c = i & 63;
        Xs[r][c] = X[((size_t)bh*T + (size_t)chunk*64 + r)*D + c];
        Ws[r][c] = W[i];
    }
    __syncthreads();

    int t  = tid & 63;        // warp-consecutive -> conflict-free Xs
    int e0 = (tid >> 6) * 16; // warp-uniform -> Ws broadcast
    float acc[16];
    #pragma unroll
    for (int k = 0; k < 16; k++) acc[k] = 0.f;

    #pragma unroll 4
    for (int d = 0; d < 64; d++) {
        float xv = Xs[t][d];
        #pragma unroll
        for (int k = 0; k < 16; k++)
            acc[k] = fmaf(xv, Ws[e0+k][d], acc[k]);
    }

    if (which) {   // key path -> fp16
        __half* outTh = (__half*)g_kpTh4;
        #pragma unroll
        for (int k = 0; k < 16; k++)
            outTh[((size_t)bh*D + e0 + k)*S + (size_t)chunk*64 + t] = __float2half_rn(acc[k]);
    } else {       // query path -> fp32
        float* outT = (float*)g_qpT4;
        #pragma unroll
        for (int k = 0; k < 16; k++)
            outT[((size_t)bh*D + e0 + k)*T + (size_t)chunk*64 + t] = acc[k];
    }
}

// ---------------------------------------------------------------------------
// Phase 2: fused score(tanh.f16x2, half2 accumulate) + softmax + attn@value
// grid (48 t-chunks, 16 bh), 128 threads. One CTA: 8 t x 384 s.
// Thread tile 4t x 3 s-pairs. kp in 4 sync chunks of 16 e; fp16 pair
// accumulators flushed to fp32 every 8 e-steps (cuts H2F cvt count 8x).
// ---------------------------------------------------------------------------
__global__ __launch_bounds__(128) void attn_kernel(
    const float* __restrict__ value, const float* __restrict__ v_w,
    float* __restrict__ out, float* __restrict__ attn)
{
    // kp chunk (16 e x 192 half2 = 12288 B), later aliased as scores[8][384] f32
    __shared__ __align__(16) unsigned char sh_raw[16*192*4];
    __shared__ __align__(8) __half2 sh_qph[64][8];   // (h,h) broadcast pairs
    __shared__ __align__(8) __half2 sh_vwh[64];      // (h,h) pairs

    __half2 (*kph)[192] = (__half2(*)[192])sh_raw;
    float  (*scores)[384] = (float(*)[384])sh_raw;

    int bh  = blockIdx.y;
    int t0  = blockIdx.x * 8;
    int tid = threadIdx.x;

    // stage qp tile as f16x2 broadcast pairs + v_w as half2
    const float* qbase = (const float*)g_qpT4 + (size_t)bh*D*T;
    for (int i = tid; i < 64*8; i += 128) {
        int e = i >> 3, tl = i & 7;
        __half h = __float2half_rn(qbase[(size_t)e*T + t0 + tl]);
        sh_qph[e][tl] = __half2half2(h);
    }
    if (tid < 64) sh_vwh[tid] = __float2half2_rn(v_w[tid]);

    int sx = tid & 63;   // s-pair lane
    int ty = tid >> 6;   // t group (warp-uniform -> qph broadcast)

    float acc[4][6];
    #pragma unroll
    for (int k = 0; k < 4; k++)
        #pragma unroll
        for (int j = 0; j < 6; j++) acc[k][j] = 0.f;

    const uint4* kbase = g_kpTh4 + (size_t)bh*D*S/8;

    for (int c = 0; c < 4; c++) {
        __syncthreads();
        // load kp chunk: 16 e-rows x 384 halfs = 768 uint4, 6/thread
        const uint4* src = kbase + (size_t)c*16*S/8;
        uint4* dst = (uint4*)sh_raw;
        #pragma unroll
        for (int i = tid; i < 768; i += 128) dst[i] = src[i];
        __syncthreads();

        #pragma unroll
        for (int half8 = 0; half8 < 2; half8++) {
            __half2 hacc[4][3];
            #pragma unroll
            for (int k = 0; k < 4; k++)
                #pragma unroll
                for (int p = 0; p < 3; p++) hacc[k][p] = __float2half2_rn(0.f);

            #pragma unroll
            for (int e8 = 0; e8 < 8; e8++) {
                int ec = half8*8 + e8;
                int e  = c*16 + ec;
                __half2 vw2 = sh_vwh[e];
                __half2 q2[4], kk[3];
                #pragma unroll
                for (int k = 0; k < 4; k++) q2[k] = sh_qph[e][ty*4 + k];
                #pragma unroll
                for (int p = 0; p < 3; p++) kk[p] = kph[ec][sx + 64*p];
                #pragma unroll
                for (int k = 0; k < 4; k++)
                    #pragma unroll
                    for (int p = 0; p < 3; p++) {
                        __half2 x = __hadd2(q2[k], kk[p]);
                        unsigned xo, xi = *(unsigned*)&x;
                        asm("tanh.approx.f16x2 %0, %1;" : "=r"(xo) : "r"(xi));
                        __half2 th = *(__half2*)&xo;
                        hacc[k][p] = __hfma2(vw2, th, hacc[k][p]);
                    }
            }
            // flush fp16 pair-accumulators to fp32
            #pragma unroll
            for (int k = 0; k < 4; k++)
                #pragma unroll
                for (int p = 0; p < 3; p++) {
                    float2 f = __half22float2(hacc[k][p]);
                    acc[k][2*p]   += f.x;
                    acc[k][2*p+1] += f.y;
                }
        }
    }
    __syncthreads();

    // dump scores (thread's s values: 2*sx + 128*p and +1) into aliased buffer
    #pragma unroll
    for (int k = 0; k < 4; k++)
        #pragma unroll
        for (int p = 0; p < 3; p++) {
            scores[ty*4+k][2*sx   + 128*p] = acc[k][2*p];
            scores[ty*4+k][2*sx+1 + 128*p] = acc[k][2*p+1];
        }
    __syncthreads();

    // softmax: 4 warps, 2 rows each; write attn to global, keep normalized in smem
    int w = tid >> 5, lane = tid & 31;
    for (int r = w; r < 8; r += 4) {
        float vals[12];
        float m = -1e30f;
        #pragma unroll
        for (int i = 0; i < 12; i++) {
            vals[i] = scores[r][lane + 32*i];
            m = fmaxf(m, vals[i]);
        }
        #pragma unroll
        for (int off = 16; off; off >>= 1)
            m = fmaxf(m, __shfl_xor_sync(0xffffffffu, m, off));
        float sum = 0.f;
        #pragma unroll
        for (int i = 0; i < 12; i++) {
            float p;
            float xe = (vals[i] - m) * 1.4426950408889634f;
            asm("ex2.approx.f32 %0, %1;" : "=f"(p) : "f"(xe));
            vals[i] = p;
            sum += p;
        }
        #pragma unroll
        for (int off = 16; off; off >>= 1)
            sum += __shfl_xor_sync(0xffffffffu, sum, off);
        float inv = 1.0f / sum;
        size_t arow = ((size_t)bh*T + t0 + r) * S;
        #pragma unroll
        for (int i = 0; i < 12; i++) {
            float p = vals[i] * inv;
            scores[r][lane + 32*i] = p;
            attn[arow + lane + 32*i] = p;
        }
    }
    __syncthreads();

    // epilogue: out[t0+tl][d] = sum_s attn[tl][s] * value[s][d]
    int dx = sx; // 0..63, warp-coalesced value loads
    float acc2[4] = {0.f, 0.f, 0.f, 0.f};
    const float* vp = value + (size_t)bh*S*D + dx;
    #pragma unroll 2
    for (int s = 0; s < 384; s += 4) {
        float v0 = __ldg(vp + (size_t)(s+0)*D);
        float v1 = __ldg(vp + (size_t)(s+1)*D);
        float v2 = __ldg(vp + (size_t)(s+2)*D);
        float v3 = __ldg(vp + (size_t)(s+3)*D);
        #pragma unroll
        for (int k = 0; k < 4; k++) {
            float4 a = *(const float4*)&scores[ty*4+k][s];
            acc2[k] = fmaf(a.x, v0, fmaf(a.y, v1, fmaf(a.z, v2, fmaf(a.w, v3, acc2[k]))));
        }
    }
    #pragma unroll
    for (int k = 0; k < 4; k++)
        out[((size_t)bh*T + t0 + ty*4 + k)*D + dx] = acc2[k];
}

// ---------------------------------------------------------------------------
extern "C" void kernel_launch(void* const* d_in, const int* in_sizes, int n_in,
                              void* d_out, int out_size)
{
    (void)in_sizes; (void)n_in; (void)out_size;
    const float* query = (const float*)d_in[0];
    const float* key   = (const float*)d_in[1];
    const float* value = (const float*)d_in[2];
    const float* Wq    = (const float*)d_in[3];
    const float* Wk    = (const float*)d_in[4];
    const float* vw    = (const float*)d_in[5];
    float* out  = (float*)d_out;
    float* attn = out + OUT_ELEMS;

    proj_kernel<<<dim3(16, 6, 2), 256>>>(query, key, Wq, Wk);
    attn_kernel<<<dim3(48, 16), 128>>>(value, vw, out, attn);
}